// round 3
// baseline (speedup 1.0000x reference)
#include <cuda_runtime.h>

#define Bn 32
#define Cn 4
#define Hn 512
#define Wn 512
#define Tn 64
#define Gn 2
#define HCHUNKS 8

// Scratch (device globals — no allocation allowed)
__device__ float  g_part[Bn * Gn * HCHUNKS * Wn];           // partial diff sums
__device__ int    g_sel[Bn * Gn * Tn];                      // selected column indices
__device__ float2 g_C[(size_t)Bn * Gn * 2 * Tn * Hn];       // ifft'd columns [b][g][ch][j][h]
__device__ float2 g_twF[256];                               // forward twiddles exp(-2pi i k/512)
__device__ float2 g_twI[256];                               // inverse twiddles exp(+2pi i k/512)

// ---------------------------------------------------------------------------
// Kernel 0: twiddle tables, once per launch (512 sincospi total).
// ---------------------------------------------------------------------------
__global__ void k_tw() {
    int k = threadIdx.x;                 // 0..255
    double s, c;
    sincospi(2.0 * (double)k / 512.0, &s, &c);
    g_twF[k] = make_float2((float)c, (float)-s);
    g_twI[k] = make_float2((float)c, (float)s);
}

// ---------------------------------------------------------------------------
// Kernel 1: diff[b,g,w] partial sums over h-chunks (deterministic, no atomics)
// ---------------------------------------------------------------------------
__global__ void k_diff(const float* __restrict__ xr, const float* __restrict__ xi) {
    int w  = threadIdx.x;        // 0..511
    int hc = blockIdx.x;         // 0..HCHUNKS-1
    int g  = blockIdx.y;         // 0..1
    int b  = blockIdx.z;         // 0..31
    int c0 = 2 * g, c1 = 2 * g + 1;

    const float* r0 = xr + (size_t)(b * Cn + c0) * Hn * Wn;
    const float* r1 = xr + (size_t)(b * Cn + c1) * Hn * Wn;
    const float* i0 = xi + (size_t)(b * Cn + c0) * Hn * Wn;
    const float* i1 = xi + (size_t)(b * Cn + c1) * Hn * Wn;

    float acc = 0.0f;
    int h0 = hc * (Hn / HCHUNKS);
    #pragma unroll 4
    for (int h = h0; h < h0 + (Hn / HCHUNKS); ++h) {
        size_t off = (size_t)h * Wn + w;
        float a = fabsf(fabsf(__ldg(r0 + off)) - fabsf(__ldg(i1 + off)));
        float c = fabsf(fabsf(__ldg(r1 + off)) - fabsf(__ldg(i0 + off)));
        acc += a + c;
    }
    g_part[(((size_t)b * Gn + g) * HCHUNKS + hc) * Wn + w] = acc;
}

// ---------------------------------------------------------------------------
// Kernel 2: select T smallest (stable-argsort semantics via rank counting)
// ---------------------------------------------------------------------------
__global__ void k_select() {
    __shared__ float d[Wn];
    int w = threadIdx.x;         // 0..511
    int g = blockIdx.x;
    int b = blockIdx.y;

    float s = 0.0f;
    #pragma unroll
    for (int k = 0; k < HCHUNKS; ++k)
        s += g_part[(((size_t)b * Gn + g) * HCHUNKS + k) * Wn + w];
    d[w] = s;
    __syncthreads();

    float mine = d[w];
    int rank = 0;
    #pragma unroll 8
    for (int u = 0; u < Wn; ++u) {
        float v = d[u];
        rank += (v < mine) || (v == mine && u < w);
    }
    if (rank < Tn) g_sel[(b * Gn + g) * Tn + rank] = w;
}

// ---------------------------------------------------------------------------
// Stockham radix-4 machinery. 128 threads, N=512, natural-order in/out.
// Buffers are separate re/im float arrays, accessed through swizzle sw() to
// kill bank conflicts. tw[k] = exp(SIGN*2*pi*i*k/512), k < 256 (smem copy).
// ---------------------------------------------------------------------------
__device__ __forceinline__ int sw(int i) { return i ^ ((i >> 5) & 3); }

template<int S, int SIGN>
__device__ __forceinline__ void r4pass(const float* __restrict__ xr,
                                       const float* __restrict__ xi,
                                       float* __restrict__ yr,
                                       float* __restrict__ yi,
                                       const float2* __restrict__ tw, int t) {
    __syncthreads();   // covers previous pass's writes (and initial fill)

    int q  = t & (S - 1);
    int pS = t - q;                    // p*S, twiddle index; < 128

    float2 w1 = tw[pS];
    float2 w2 = tw[2 * pS];
    float  w3r = w1.x * w2.x - w1.y * w2.y;
    float  w3i = w1.x * w2.y + w1.y * w2.x;

    float ar = xr[sw(t)],       ai = xi[sw(t)];
    float br = xr[sw(t + 128)], bi = xi[sw(t + 128)];
    float cr = xr[sw(t + 256)], ci = xi[sw(t + 256)];
    float dr = xr[sw(t + 384)], di = xi[sw(t + 384)];

    float Apr = ar + cr, Api = ai + ci;   // a + c
    float Bpr = ar - cr, Bpi = ai - ci;   // a - c
    float Cpr = br + dr, Cpi = bi + di;   // b + d
    float Epr = br - dr, Epi = bi - di;   // b - d

    // j0 = A + C ; j2 = (A - C) ; j1 = B - SIGN?  (fwd: B - iE, inv: B + iE)
    float y0r = Apr + Cpr, y0i = Api + Cpi;
    float u2r = Apr - Cpr, u2i = Api - Cpi;
    const float SG = (float)SIGN;           // -1 fwd, +1 inv
    float j1r = Bpr - SG * Epi, j1i = Bpi + SG * Epr;   // fwd: (B.r+E.i, B.i-E.r)
    float j3r = Bpr + SG * Epi, j3i = Bpi - SG * Epr;

    int base = 4 * t - 3 * q;          // s*4p + q

    yr[sw(base)]         = y0r;
    yi[sw(base)]         = y0i;
    yr[sw(base + S)]     = w1.x * j1r - w1.y * j1i;
    yi[sw(base + S)]     = w1.x * j1i + w1.y * j1r;
    yr[sw(base + 2 * S)] = w2.x * u2r - w2.y * u2i;
    yi[sw(base + 2 * S)] = w2.x * u2i + w2.y * u2r;
    yr[sw(base + 3 * S)] = w3r * j3r - w3i * j3i;
    yi[sw(base + 3 * S)] = w3r * j3i + w3i * j3r;
}

// ---------------------------------------------------------------------------
// Kernel 3: IFFT along H of each selected column. One block (128 thr) per
// (b,g,ch,j). Natural-order load -> 4 radix-4 passes -> fused radix-2 + store.
// ---------------------------------------------------------------------------
__global__ void k_ifft(const float* __restrict__ xr, const float* __restrict__ xi) {
    __shared__ float Ar[Hn], Ai[Hn], Br_[Hn], Bi_[Hn];
    __shared__ float2 stw[256];
    int t   = threadIdx.x;       // 0..127
    int j   = blockIdx.x;        // 0..63
    int gc  = blockIdx.y;        // 0..3 = g*2+ch
    int b   = blockIdx.z;
    int g = gc >> 1, ch = gc & 1;
    int c = 2 * g + ch;
    int wj = g_sel[(b * Gn + g) * Tn + j];

    stw[t]       = g_twI[t];
    stw[t + 128] = g_twI[t + 128];

    const float* pr = xr + (size_t)(b * Cn + c) * Hn * Wn + wj;
    const float* pi = xi + (size_t)(b * Cn + c) * Hn * Wn + wj;
    #pragma unroll
    for (int k = 0; k < 4; ++k) {
        int h = t + k * 128;
        Ar[sw(h)] = __ldg(pr + (size_t)h * Wn);
        Ai[sw(h)] = __ldg(pi + (size_t)h * Wn);
    }

    r4pass<1,  1>(Ar, Ai, Br_, Bi_, stw, t);   // leading sync covers fill
    r4pass<4,  1>(Br_, Bi_, Ar, Ai, stw, t);
    r4pass<16, 1>(Ar, Ai, Br_, Bi_, stw, t);
    r4pass<64, 1>(Br_, Bi_, Ar, Ai, stw, t);
    __syncthreads();

    // Fused final radix-2 (n=2, s=256, twiddle=1) + scale + store
    const float scale = 1.0f / 512.0f;
    float2* out = g_C + ((((size_t)b * Gn + g) * 2 + ch) * Tn + j) * Hn;
    #pragma unroll
    for (int k = 0; k < 2; ++k) {
        int q = t + k * 128;
        float xr0 = Ar[sw(q)],       xi0 = Ai[sw(q)];
        float xr1 = Ar[sw(q + 256)], xi1 = Ai[sw(q + 256)];
        out[q]       = make_float2((xr0 + xr1) * scale, (xi0 + xi1) * scale);
        out[q + 256] = make_float2((xr0 - xr1) * scale, (xi0 - xi1) * scale);
    }
}

// ---------------------------------------------------------------------------
// Kernel 4: per output row, scatter 64 values + forward FFT along W, +0.5.
// One block (128 thr) per (b,c,h).
// ---------------------------------------------------------------------------
__global__ void k_out(float2* __restrict__ out) {
    __shared__ float Ar[Wn], Ai[Wn], Br_[Wn], Bi_[Wn];
    __shared__ float2 stw[256];
    int t = threadIdx.x;         // 0..127
    int h = blockIdx.x;          // 0..511
    int c = blockIdx.y;          // 0..3
    int b = blockIdx.z;
    int g = c >> 1, ch = c & 1;

    stw[t]       = g_twF[t];
    stw[t + 128] = g_twF[t + 128];
    #pragma unroll
    for (int k = 0; k < 4; ++k) {
        Ar[t + k * 128] = 0.0f;
        Ai[t + k * 128] = 0.0f;
    }
    __syncthreads();

    if (t < Tn) {
        int idx  = g_sel[(b * Gn + g) * Tn + t];
        float2 v = g_C[((((size_t)b * Gn + g) * 2 + ch) * Tn + t) * Hn + h];
        Ar[sw(idx)] = v.x;
        Ai[sw(idx)] = v.y;
    }

    r4pass<1,  -1>(Ar, Ai, Br_, Bi_, stw, t);   // leading sync covers scatter
    r4pass<4,  -1>(Br_, Bi_, Ar, Ai, stw, t);
    r4pass<16, -1>(Ar, Ai, Br_, Bi_, stw, t);
    r4pass<64, -1>(Br_, Bi_, Ar, Ai, stw, t);
    __syncthreads();

    // Fused final radix-2 + (+0.5 on real) + store
    float2* o = out + ((size_t)(b * Cn + c) * Hn + h) * Wn;
    #pragma unroll
    for (int k = 0; k < 2; ++k) {
        int q = t + k * 128;
        float xr0 = Ar[sw(q)],       xi0 = Ai[sw(q)];
        float xr1 = Ar[sw(q + 256)], xi1 = Ai[sw(q + 256)];
        o[q]       = make_float2(xr0 + xr1 + 0.5f, xi0 + xi1);
        o[q + 256] = make_float2(xr0 - xr1 + 0.5f, xi0 - xi1);
    }
}

// ---------------------------------------------------------------------------
extern "C" void kernel_launch(void* const* d_in, const int* in_sizes, int n_in,
                              void* d_out, int out_size) {
    const float* xr = (const float*)d_in[0];
    const float* xi = (const float*)d_in[1];

    k_tw    <<<1, 256>>>();
    k_diff  <<<dim3(HCHUNKS, Gn, Bn), Wn>>>(xr, xi);
    k_select<<<dim3(Gn, Bn), Wn>>>();
    k_ifft  <<<dim3(Tn, Gn * 2, Bn), 128>>>(xr, xi);
    k_out   <<<dim3(Hn, Cn, Bn), 128>>>((float2*)d_out);
}

// round 16
// speedup vs baseline: 1.1052x; 1.1052x over previous
#include <cuda_runtime.h>

#define Bn 32
#define Cn 4
#define Hn 512
#define Wn 512
#define Tn 64
#define Gn 2
#define HCHUNKS 8

// Scratch (device globals — no allocation allowed)
__device__ float  g_part[Bn * Gn * HCHUNKS * Wn];           // partial diff sums
__device__ int    g_sel[Bn * Gn * Tn];                      // selected column indices
__device__ float2 g_C[(size_t)Bn * Gn * 2 * Tn * Hn];       // ifft'd columns [b][g][ch][j][h]
__device__ float2 g_twF[256];                               // forward twiddles exp(-2pi i k/512)
__device__ float2 g_twI[256];                               // inverse twiddles exp(+2pi i k/512)

// ---------------------------------------------------------------------------
// Kernel 1: diff[b,g,w] partial sums over h-chunks (deterministic, no atomics)
// ---------------------------------------------------------------------------
__global__ void k_diff(const float* __restrict__ xr, const float* __restrict__ xi) {
    int w  = threadIdx.x;        // 0..511
    int hc = blockIdx.x;         // 0..HCHUNKS-1
    int g  = blockIdx.y;         // 0..1
    int b  = blockIdx.z;         // 0..31
    int c0 = 2 * g, c1 = 2 * g + 1;

    const float* r0 = xr + (size_t)(b * Cn + c0) * Hn * Wn;
    const float* r1 = xr + (size_t)(b * Cn + c1) * Hn * Wn;
    const float* i0 = xi + (size_t)(b * Cn + c0) * Hn * Wn;
    const float* i1 = xi + (size_t)(b * Cn + c1) * Hn * Wn;

    float acc = 0.0f;
    int h0 = hc * (Hn / HCHUNKS);
    #pragma unroll 4
    for (int h = h0; h < h0 + (Hn / HCHUNKS); ++h) {
        size_t off = (size_t)h * Wn + w;
        float a = fabsf(fabsf(__ldg(r0 + off)) - fabsf(__ldg(i1 + off)));
        float c = fabsf(fabsf(__ldg(r1 + off)) - fabsf(__ldg(i0 + off)));
        acc += a + c;
    }
    g_part[(((size_t)b * Gn + g) * HCHUNKS + hc) * Wn + w] = acc;
}

// ---------------------------------------------------------------------------
// Kernel 2: select T smallest (stable-argsort semantics via rank counting).
// Block (g=0,b=0) additionally fills the twiddle tables (consumed only by
// the later k_ifft / k_out launches — stream order guarantees visibility).
// ---------------------------------------------------------------------------
__global__ void k_select() {
    __shared__ float d[Wn];
    int w = threadIdx.x;         // 0..511
    int g = blockIdx.x;
    int b = blockIdx.y;

    if (g == 0 && b == 0 && w < 256) {
        double s, c;
        sincospi(2.0 * (double)w / 512.0, &s, &c);
        g_twF[w] = make_float2((float)c, (float)-s);
        g_twI[w] = make_float2((float)c, (float)s);
    }

    float s = 0.0f;
    #pragma unroll
    for (int k = 0; k < HCHUNKS; ++k)
        s += g_part[(((size_t)b * Gn + g) * HCHUNKS + k) * Wn + w];
    d[w] = s;
    __syncthreads();

    float mine = d[w];
    int rank = 0;
    #pragma unroll 8
    for (int u = 0; u < Wn; ++u) {
        float v = d[u];
        rank += (v < mine) || (v == mine && u < w);
    }
    if (rank < Tn) g_sel[(b * Gn + g) * Tn + rank] = w;
}

// ---------------------------------------------------------------------------
// Stockham radix-4 machinery (used by k_ifft; unchanged, known-passing).
// ---------------------------------------------------------------------------
__device__ __forceinline__ int sw(int i) { return i ^ ((i >> 5) & 3); }

template<int S, int SIGN>
__device__ __forceinline__ void r4pass(const float* __restrict__ xr,
                                       const float* __restrict__ xi,
                                       float* __restrict__ yr,
                                       float* __restrict__ yi,
                                       const float2* __restrict__ tw, int t) {
    __syncthreads();   // covers previous pass's writes (and initial fill)

    int q  = t & (S - 1);
    int pS = t - q;                    // p*S, twiddle index; < 128

    float2 w1 = tw[pS];
    float2 w2 = tw[2 * pS];
    float  w3r = w1.x * w2.x - w1.y * w2.y;
    float  w3i = w1.x * w2.y + w1.y * w2.x;

    float ar = xr[sw(t)],       ai = xi[sw(t)];
    float br = xr[sw(t + 128)], bi = xi[sw(t + 128)];
    float cr = xr[sw(t + 256)], ci = xi[sw(t + 256)];
    float dr = xr[sw(t + 384)], di = xi[sw(t + 384)];

    float Apr = ar + cr, Api = ai + ci;
    float Bpr = ar - cr, Bpi = ai - ci;
    float Cpr = br + dr, Cpi = bi + di;
    float Epr = br - dr, Epi = bi - di;

    float y0r = Apr + Cpr, y0i = Api + Cpi;
    float u2r = Apr - Cpr, u2i = Api - Cpi;
    const float SG = (float)SIGN;           // -1 fwd, +1 inv
    float j1r = Bpr - SG * Epi, j1i = Bpi + SG * Epr;
    float j3r = Bpr + SG * Epi, j3i = Bpi - SG * Epr;

    int base = 4 * t - 3 * q;          // s*4p + q

    yr[sw(base)]         = y0r;
    yi[sw(base)]         = y0i;
    yr[sw(base + S)]     = w1.x * j1r - w1.y * j1i;
    yi[sw(base + S)]     = w1.x * j1i + w1.y * j1r;
    yr[sw(base + 2 * S)] = w2.x * u2r - w2.y * u2i;
    yi[sw(base + 2 * S)] = w2.x * u2i + w2.y * u2r;
    yr[sw(base + 3 * S)] = w3r * j3r - w3i * j3i;
    yi[sw(base + 3 * S)] = w3r * j3i + w3i * j3r;
}

// ---------------------------------------------------------------------------
// Kernel 3: IFFT along H of each selected column. One block (128 thr) per
// (b,g,ch,j). Natural-order load -> 4 radix-4 passes -> fused radix-2 + store.
// ---------------------------------------------------------------------------
__global__ void k_ifft(const float* __restrict__ xr, const float* __restrict__ xi) {
    __shared__ float Ar[Hn], Ai[Hn], Br_[Hn], Bi_[Hn];
    __shared__ float2 stw[256];
    int t   = threadIdx.x;       // 0..127
    int j   = blockIdx.x;        // 0..63
    int gc  = blockIdx.y;        // 0..3 = g*2+ch
    int b   = blockIdx.z;
    int g = gc >> 1, ch = gc & 1;
    int c = 2 * g + ch;
    int wj = g_sel[(b * Gn + g) * Tn + j];

    stw[t]       = g_twI[t];
    stw[t + 128] = g_twI[t + 128];

    const float* pr = xr + (size_t)(b * Cn + c) * Hn * Wn + wj;
    const float* pi = xi + (size_t)(b * Cn + c) * Hn * Wn + wj;
    #pragma unroll
    for (int k = 0; k < 4; ++k) {
        int h = t + k * 128;
        Ar[sw(h)] = __ldg(pr + (size_t)h * Wn);
        Ai[sw(h)] = __ldg(pi + (size_t)h * Wn);
    }

    r4pass<1,  1>(Ar, Ai, Br_, Bi_, stw, t);
    r4pass<4,  1>(Br_, Bi_, Ar, Ai, stw, t);
    r4pass<16, 1>(Ar, Ai, Br_, Bi_, stw, t);
    r4pass<64, 1>(Br_, Bi_, Ar, Ai, stw, t);
    __syncthreads();

    const float scale = 1.0f / 512.0f;
    float2* out = g_C + ((((size_t)b * Gn + g) * 2 + ch) * Tn + j) * Hn;
    #pragma unroll
    for (int k = 0; k < 2; ++k) {
        int q = t + k * 128;
        float xr0 = Ar[sw(q)],       xi0 = Ai[sw(q)];
        float xr1 = Ar[sw(q + 256)], xi1 = Ai[sw(q + 256)];
        out[q]       = make_float2((xr0 + xr1) * scale, (xi0 + xi1) * scale);
        out[q + 256] = make_float2((xr0 - xr1) * scale, (xi0 - xi1) * scale);
    }
}

// ---------------------------------------------------------------------------
// Kernel 4: warp-level 512-pt forward FFT, 1 warp = 1 output row.
// N = 32 (lanes) x 16 (registers):
//   x[16*n1 + n2], n1 = lane, n2 = reg.
//   (1) 32-pt DIF across lanes via 5 shfl_xor stages  -> lane holds k1=brev5(l)
//   (2) twiddle W512^(n2*k1)
//   (3) 16-pt FFT in registers (2x radix-4 DIF, hardcoded W16 constants),
//       register q holds k2 = (q>>2) + 4*(q&3)
//   X[k1 + 32*k2]; store +0.5 on real, coalesced per 256B block.
// 8 warps/block = 8 h rows; per-warp smem staging only for the 64-pt scatter.
// ---------------------------------------------------------------------------
__device__ __forceinline__ int brev5(int x) { return __brev((unsigned)x) >> 27; }

__global__ void __launch_bounds__(256) k_out(float2* __restrict__ out) {
    __shared__ float2 stw[512];          // W512^k, forward, full table
    __shared__ int    sel_s[Tn];
    __shared__ float2 stage[8][32][17];  // per-warp padded scatter buffer

    int tid = threadIdx.x;               // 0..255
    int wid = tid >> 5;                  // 0..7
    int l   = tid & 31;                  // lane
    int c   = blockIdx.y;                // 0..3
    int b   = blockIdx.z;
    int g = c >> 1, ch = c & 1;
    int h = blockIdx.x * 8 + wid;        // 0..511

    // Block-shared setup
    {
        float2 w = g_twF[tid];
        stw[tid]       = w;
        stw[tid + 256] = make_float2(-w.x, -w.y);     // W^(k+256) = -W^k
    }
    if (tid < Tn) sel_s[tid] = g_sel[(b * Gn + g) * Tn + tid];
    __syncthreads();

    // ---- per-warp scatter staging: x[16*n1 + n2] at stage[wid][n1][n2] ----
    float2 (*st)[17] = stage[wid];
    #pragma unroll
    for (int j = 0; j < 16; ++j) st[l][j] = make_float2(0.0f, 0.0f);
    __syncwarp();

    {
        size_t cb = (((size_t)b * Gn + g) * 2 + ch) * Tn;
        int   i0 = sel_s[l],        i1 = sel_s[l + 32];
        float2 v0 = __ldg((const float2*)g_C + (cb + l)      * Hn + h);
        float2 v1 = __ldg((const float2*)g_C + (cb + l + 32) * Hn + h);
        st[i0 >> 4][i0 & 15] = v0;
        st[i1 >> 4][i1 & 15] = v1;
    }
    __syncwarp();

    float vr[16], vi[16];
    #pragma unroll
    for (int j = 0; j < 16; ++j) { float2 v = st[l][j]; vr[j] = v.x; vi[j] = v.y; }

    // ---- (1) 32-pt DIF across lanes (Gentleman-Sande), 5 stages ----
    const unsigned FULL = 0xffffffffu;
    #pragma unroll
    for (int st5 = 0; st5 < 5; ++st5) {
        int d = 16 >> st5;                       // 16,8,4,2,1
        bool up = (l & d) != 0;
        float2 tw = stw[(l & (d - 1)) * (256 / d)];
        #pragma unroll
        for (int j = 0; j < 16; ++j) {
            float orr = __shfl_xor_sync(FULL, vr[j], d);
            float oii = __shfl_xor_sync(FULL, vi[j], d);
            float sr = vr[j] + orr, si = vi[j] + oii;          // lower result
            float dr = orr - vr[j], di = oii - vi[j];          // (lower - upper)
            float ur = dr * tw.x - di * tw.y;
            float ui = dr * tw.y + di * tw.x;
            vr[j] = up ? ur : sr;
            vi[j] = up ? ui : si;
        }
    }
    int k1 = brev5(l);

    // ---- (2) twiddle W512^(n2*k1) ----
    #pragma unroll
    for (int j = 1; j < 16; ++j) {
        float2 tw = stw[(j * k1) & 511];
        float r = vr[j] * tw.x - vi[j] * tw.y;
        float i = vr[j] * tw.y + vi[j] * tw.x;
        vr[j] = r; vi[j] = i;
    }

    // ---- (3) 16-pt FFT in registers: 2x radix-4 DIF ----
    const float C1 =  0.92387953251128674f, S1 = -0.38268343236508978f; // W16^1
    const float C2 =  0.70710678118654752f, S2 = -0.70710678118654752f; // W16^2
    const float C3 =  0.38268343236508978f, S3 = -0.92387953251128674f; // W16^3

    // Stage 1: butterflies over (p, p+4, p+8, p+12), twiddle W16^{p*m}
    #pragma unroll
    for (int p = 0; p < 4; ++p) {
        float t0r = vr[p]   + vr[p+8],  t0i = vi[p]   + vi[p+8];
        float t1r = vr[p]   - vr[p+8],  t1i = vi[p]   - vi[p+8];
        float t2r = vr[p+4] + vr[p+12], t2i = vi[p+4] + vi[p+12];
        float t3r = vr[p+4] - vr[p+12], t3i = vi[p+4] - vi[p+12];
        float u0r = t0r + t2r, u0i = t0i + t2i;
        float u1r = t1r + t3i, u1i = t1i - t3r;     // t1 - i*t3
        float u2r = t0r - t2r, u2i = t0i - t2i;
        float u3r = t1r - t3i, u3i = t1i + t3r;     // t1 + i*t3
        float w1r, w1i, w2r, w2i, w3r, w3i;
        if      (p == 0) { w1r=1;  w1i=0;  w2r=1;   w2i=0;  w3r=1;   w3i=0;  }
        else if (p == 1) { w1r=C1; w1i=S1; w2r=C2;  w2i=S2; w3r=C3;  w3i=S3; }
        else if (p == 2) { w1r=C2; w1i=S2; w2r=0;   w2i=-1; w3r=-C2; w3i=S2; }
        else             { w1r=C3; w1i=S3; w2r=-C2; w2i=S2; w3r=-C1; w3i=-S1;}
        vr[p]    = u0r;                      vi[p]    = u0i;
        vr[p+4]  = u1r*w1r - u1i*w1i;        vi[p+4]  = u1r*w1i + u1i*w1r;
        vr[p+8]  = u2r*w2r - u2i*w2i;        vi[p+8]  = u2r*w2i + u2i*w2r;
        vr[p+12] = u3r*w3r - u3i*w3i;        vi[p+12] = u3r*w3i + u3i*w3r;
    }
    // Stage 2: radix-4 on consecutive quads, no twiddle
    #pragma unroll
    for (int s = 0; s < 4; ++s) {
        int q0 = 4 * s;
        float t0r = vr[q0]   + vr[q0+2], t0i = vi[q0]   + vi[q0+2];
        float t1r = vr[q0]   - vr[q0+2], t1i = vi[q0]   - vi[q0+2];
        float t2r = vr[q0+1] + vr[q0+3], t2i = vi[q0+1] + vi[q0+3];
        float t3r = vr[q0+1] - vr[q0+3], t3i = vi[q0+1] - vi[q0+3];
        vr[q0]   = t0r + t2r;  vi[q0]   = t0i + t2i;
        vr[q0+1] = t1r + t3i;  vi[q0+1] = t1i - t3r;   // t1 - i*t3
        vr[q0+2] = t0r - t2r;  vi[q0+2] = t0i - t2i;
        vr[q0+3] = t1r - t3i;  vi[q0+3] = t1i + t3r;   // t1 + i*t3
    }

    // ---- store: register q holds k2 = (q>>2) + 4*(q&3); w = k1 + 32*k2 ----
    float2* o = out + ((size_t)(b * Cn + c) * Hn + h) * Wn;
    #pragma unroll
    for (int q = 0; q < 16; ++q) {
        int k2 = (q >> 2) + 4 * (q & 3);
        o[k1 + 32 * k2] = make_float2(vr[q] + 0.5f, vi[q]);
    }
}

// ---------------------------------------------------------------------------
extern "C" void kernel_launch(void* const* d_in, const int* in_sizes, int n_in,
                              void* d_out, int out_size) {
    const float* xr = (const float*)d_in[0];
    const float* xi = (const float*)d_in[1];

    k_diff  <<<dim3(HCHUNKS, Gn, Bn), Wn>>>(xr, xi);
    k_select<<<dim3(Gn, Bn), Wn>>>();
    k_ifft  <<<dim3(Tn, Gn * 2, Bn), 128>>>(xr, xi);
    k_out   <<<dim3(Hn / 8, Cn, Bn), 256>>>((float2*)d_out);
}